// round 11
// baseline (speedup 1.0000x reference)
#include <cuda_runtime.h>
#include <cuda_fp16.h>
#include <math.h>
#include <stdint.h>

#define D   128
#define G   4096
#define S   3
#define MAXN 1000000

// ---------------- device scratch ----------------
__device__ float d_gates[S * MAXN];
__device__ float d_alpha[S * MAXN];
__device__ int   d_segstart[G + 1];
__device__ float d_pooled[S * G * D];
__device__ __half d_wt_hi[S * D * D];   // W^T fp16  [s][n][k]

// ---------------- helpers ----------------
__device__ __forceinline__ uint32_t smem_u32(const void* p) {
    uint32_t a;
    asm("{ .reg .u64 t; cvta.to.shared.u64 t, %1; cvt.u32.u64 %0, t; }" : "=r"(a) : "l"(p));
    return a;
}

__device__ __forceinline__ void ldsm_x4(uint32_t* r, uint32_t addr) {
    asm volatile("ldmatrix.sync.aligned.m8n8.x4.shared.b16 {%0,%1,%2,%3}, [%4];"
                 : "=r"(r[0]), "=r"(r[1]), "=r"(r[2]), "=r"(r[3]) : "r"(addr));
}

__device__ __forceinline__ void mma16816(float* c, const uint32_t* a, uint32_t b0, uint32_t b1) {
    asm volatile(
        "mma.sync.aligned.m16n8k16.row.col.f32.f16.f16.f32 "
        "{%0,%1,%2,%3}, {%4,%5,%6,%7}, {%8,%9}, {%0,%1,%2,%3};"
        : "+f"(c[0]), "+f"(c[1]), "+f"(c[2]), "+f"(c[3])
        : "r"(a[0]), "r"(a[1]), "r"(a[2]), "r"(a[3]), "r"(b0), "r"(b1));
}

__device__ __forceinline__ void cp_async16(uint32_t dst, const void* src, int src_bytes) {
    asm volatile("cp.async.cg.shared.global [%0], [%1], 16, %2;"
                 :: "r"(dst), "l"(src), "r"(src_bytes) : "memory");
}
#define CP_COMMIT() asm volatile("cp.async.commit_group;" ::: "memory")
#define CP_WAIT0()  asm volatile("cp.async.wait_group 0;" ::: "memory")

// swizzled byte offset within a [128 row][128 fp16] tile (row stride 256B)
__device__ __forceinline__ uint32_t swz(int row, int kbyte) {
    return ((uint32_t)row << 8) + ((uint32_t)kbyte ^ (((uint32_t)row & 7u) << 4));
}

// ---------------- smem layout (bytes) ----------------
#define SM_A      0              // 32KB: x tile fp16 (persistent across steps)
#define SM_B      32768          // 32KB: W^T fp16 (cp.async pipeline)
#define SM_STG    65536          // 34KB: fp16 staging, 128 rows x 136-half stride
#define SM_ALPHA  100352         // 3*128 fp32
#define SM_BIAS   101888         // 3*128 fp32
#define SM_GID    103424         // 128 int
#define SMEM_TOTAL 103936
#define STG_LDH   136            // halves per staging row

// ---------------- kernel A: gate dots + x copy + misc (merged) ----------------
#define MISC_COPY_BLKS  (G * D / 256)             // 2048
#define MISC_PREP_BLKS  ((S * D * D + 255) / 256) // 192
#define MISC_SEG_BLKS   ((G + 256) / 256)         // 17
#define MISC_BLKS (MISC_COPY_BLKS + MISC_PREP_BLKS + MISC_SEG_BLKS)

__global__ void k_gate_misc(const float* __restrict__ x,
                            const float* __restrict__ gate_w,
                            const float* __restrict__ gate_b,
                            float* __restrict__ out_x,
                            const float* __restrict__ xg, float* __restrict__ out_xg,
                            const float* __restrict__ feat_w,
                            const int* __restrict__ batch, int N) {
    int gate_blks = (N + 7) / 8;
    if ((int)blockIdx.x >= gate_blks) {
        // ---- misc section ----
        int b = blockIdx.x - gate_blks, t = threadIdx.x;
        if (b < MISC_COPY_BLKS) {
            out_xg[b * 256 + t] = xg[b * 256 + t];
        } else if (b < MISC_COPY_BLKS + MISC_PREP_BLKS) {
            int i = (b - MISC_COPY_BLKS) * 256 + t;
            if (i < S * D * D) {
                int s = i / (D * D), r = i % (D * D);
                int n = r / D, k = r % D;
                d_wt_hi[i] = __float2half_rn(feat_w[s * D * D + k * D + n]);
            }
        } else {
            int g = (b - MISC_COPY_BLKS - MISC_PREP_BLKS) * 256 + t;
            if (g > G) return;
            if (g == G) { d_segstart[G] = N; return; }
            int lo = 0, hi = N;
            while (lo < hi) {
                int mid = (lo + hi) >> 1;
                if (batch[mid] < g) lo = mid + 1; else hi = mid;
            }
            d_segstart[g] = lo;
        }
        return;
    }
    // ---- gate + copy section ----
    __shared__ float gw[S * D];
    int tid = threadIdx.x;
    for (int i = tid; i < S * D; i += blockDim.x) gw[i] = gate_w[i];
    __syncthreads();
    int lane = tid & 31;
    int node = blockIdx.x * 8 + (tid >> 5);
    if (node >= N) return;
    const float4 v = ((const float4*)(x + (size_t)node * D))[lane];
    ((float4*)(out_x + (size_t)node * D))[lane] = v;
#pragma unroll
    for (int s = 0; s < S; ++s) {
        const float* g = gw + s * D + lane * 4;
        float d = v.x * g[0] + v.y * g[1] + v.z * g[2] + v.w * g[3];
#pragma unroll
        for (int o = 16; o > 0; o >>= 1) d += __shfl_xor_sync(0xffffffffu, d, o);
        if (lane == 0) d_gates[s * N + node] = d + gate_b[s];
    }
}

// ---------------- kernel C: per-graph softmax -> alpha; zero pooled ----------------
__global__ void k_softmax(int N) {
    int g = blockIdx.x, t = threadIdx.x;
#pragma unroll
    for (int s = 0; s < S; ++s) d_pooled[(s * G + g) * D + t] = 0.f;
    int a = d_segstart[g], b = d_segstart[g + 1];
    if (a >= b) return;
    __shared__ float red[S][4];
    int wid = t >> 5, lane = t & 31;
    float mx[S];
#pragma unroll
    for (int s = 0; s < S; ++s) mx[s] = -INFINITY;
    for (int i = a + t; i < b; i += 128)
#pragma unroll
        for (int s = 0; s < S; ++s) mx[s] = fmaxf(mx[s], d_gates[s * N + i]);
#pragma unroll
    for (int s = 0; s < S; ++s) {
#pragma unroll
        for (int o = 16; o > 0; o >>= 1) mx[s] = fmaxf(mx[s], __shfl_xor_sync(~0u, mx[s], o));
        if (lane == 0) red[s][wid] = mx[s];
    }
    __syncthreads();
#pragma unroll
    for (int s = 0; s < S; ++s)
        mx[s] = fmaxf(fmaxf(red[s][0], red[s][1]), fmaxf(red[s][2], red[s][3]));
    __syncthreads();
    float sm[S] = {0.f, 0.f, 0.f};
    for (int i = a + t; i < b; i += 128)
#pragma unroll
        for (int s = 0; s < S; ++s) sm[s] += expf(d_gates[s * N + i] - mx[s]);
#pragma unroll
    for (int s = 0; s < S; ++s) {
#pragma unroll
        for (int o = 16; o > 0; o >>= 1) sm[s] += __shfl_xor_sync(~0u, sm[s], o);
        if (lane == 0) red[s][wid] = sm[s];
    }
    __syncthreads();
    float inv[S];
#pragma unroll
    for (int s = 0; s < S; ++s)
        inv[s] = 1.f / (red[s][0] + red[s][1] + red[s][2] + red[s][3]);
    for (int i = a + t; i < b; i += 128)
#pragma unroll
        for (int s = 0; s < S; ++s)
            d_alpha[s * N + i] = expf(d_gates[s * N + i] - mx[s]) * inv[s];
}

// ---------------- kernel D: pipelined fp16 HMMA, in-kernel A convert ----------------
__global__ void __launch_bounds__(512, 2)
k_feat_pool(const float* __restrict__ x,
            const float* __restrict__ feat_b,
            const int* __restrict__ batch, int N) {
    extern __shared__ char smem[];
    uint32_t sm = smem_u32(smem);
    __half* stg    = (__half*)(smem + SM_STG);
    float* s_alpha = (float*)(smem + SM_ALPHA);
    float* s_bias  = (float*)(smem + SM_BIAS);
    int*   s_gid   = (int*)(smem + SM_GID);

    int tid = threadIdx.x;
    int wid = tid >> 5, lane = tid & 31;
    int r0 = blockIdx.x * 128;
    int rows = min(128, N - r0);

    // ---- prologue: B(0) via cp.async; A fp32 -> fp16 convert + STS ----
    {
        const __half* wh = d_wt_hi;        // step 0
#pragma unroll
        for (int i = 0; i < 4; ++i) {
            int idx = i * 512 + tid;
            int row = idx >> 4, kpart = idx & 15;
            cp_async16(sm + SM_B + swz(row, kpart * 16), wh + row * D + kpart * 8, 16);
        }
    }
    CP_COMMIT();
#pragma unroll
    for (int i = 0; i < 8; ++i) {
        int idx = i * 512 + tid;           // 4096 float4
        int row = idx >> 5, j = idx & 31;
        float4 v = make_float4(0.f, 0.f, 0.f, 0.f);
        if (row < rows) v = ((const float4*)(x + (size_t)(r0 + row) * D))[j];
        uint2 hp;
        hp.x = (uint32_t)__half_as_ushort(__float2half_rn(v.x)) |
               ((uint32_t)__half_as_ushort(__float2half_rn(v.y)) << 16);
        hp.y = (uint32_t)__half_as_ushort(__float2half_rn(v.z)) |
               ((uint32_t)__half_as_ushort(__float2half_rn(v.w)) << 16);
        *(uint2*)(smem + SM_A + swz(row, j * 8)) = hp;
    }

    // prefetch alpha/bias for all 3 steps + gid
    if (tid < 384) {
        int s = tid >> 7, t = tid & 127;
        s_bias[tid]  = feat_b[s * D + t];
        s_alpha[tid] = (t < rows) ? d_alpha[s * N + r0 + t] : 0.f;
    }
    if (tid < 128) {
        int rr = min(tid, rows - 1);
        s_gid[tid] = batch[r0 + rr];
    }

    // warp tiling: 4 m-blocks (32 rows) x 4 n-blocks (32 cols), 16 warps
    int mbase = (wid & 3) * 32;
    int nbase = (wid >> 2) * 32;
    int r15 = lane & 15;
    uint32_t swx = ((uint32_t)lane & 7u) << 4;
    int khalf = (lane >> 4) << 4;
    int grp   = lane >> 2, tc = (lane & 3) * 2;

#pragma unroll 1
    for (int s = 0; s < S; ++s) {
        CP_WAIT0();
        __syncthreads();   // B(s) (+ s==0: A, alpha, bias, gid) ready; stg free

        float c[8][4];   // [mi*4 + nq*2 + j][4]
#pragma unroll
        for (int i = 0; i < 8; ++i)
#pragma unroll
            for (int j = 0; j < 4; ++j) c[i][j] = 0.f;

        // ---- MMA: c = x_hi * W_hi ----
#pragma unroll
        for (int ks = 0; ks < 8; ++ks) {
            int kb = ks * 32 + khalf;
            uint32_t ah[2][4];
#pragma unroll
            for (int mi = 0; mi < 2; ++mi) {
                uint32_t aoff = ((uint32_t)(mbase + mi * 16 + r15) << 8) + ((uint32_t)kb ^ swx);
                ldsm_x4(ah[mi], sm + SM_A + aoff);
            }
#pragma unroll
            for (int nq = 0; nq < 2; ++nq) {
                uint32_t bh[4];
                uint32_t boff = ((uint32_t)(nbase + nq * 16 + r15) << 8) + ((uint32_t)kb ^ swx);
                ldsm_x4(bh, sm + SM_B + boff);
#pragma unroll
                for (int mi = 0; mi < 2; ++mi) {
                    mma16816(c[mi * 4 + nq * 2],     ah[mi], bh[0], bh[2]);
                    mma16816(c[mi * 4 + nq * 2 + 1], ah[mi], bh[1], bh[3]);
                }
            }
        }
        __syncthreads();   // all warps done reading B(s)

        // ---- prefetch B(s+1), overlapped with epilogue + pooling ----
        if (s + 1 < S) {
            const __half* wh = d_wt_hi + (s + 1) * D * D;
#pragma unroll
            for (int i = 0; i < 4; ++i) {
                int idx = i * 512 + tid;
                int row = idx >> 4, kpart = idx & 15;
                cp_async16(sm + SM_B + swz(row, kpart * 16), wh + row * D + kpart * 8, 16);
            }
            CP_COMMIT();
        }

        // ---- single-phase epilogue: bias + leaky + alpha -> fp16 staging ----
#pragma unroll
        for (int mi = 0; mi < 2; ++mi) {
            int row0 = mbase + mi * 16 + grp;
            float a0 = s_alpha[s * 128 + row0], a1 = s_alpha[s * 128 + row0 + 8];
#pragma unroll
            for (int nq = 0; nq < 2; ++nq) {
#pragma unroll
                for (int j = 0; j < 2; ++j) {
                    int col = nbase + nq * 16 + j * 8 + tc;
                    float b0 = s_bias[s * 128 + col], b1 = s_bias[s * 128 + col + 1];
                    float* C = c[mi * 4 + nq * 2 + j];
                    float v0 = C[0] + b0; v0 = v0 >= 0.f ? v0 : 0.01f * v0;
                    float v1 = C[1] + b1; v1 = v1 >= 0.f ? v1 : 0.01f * v1;
                    float v2 = C[2] + b0; v2 = v2 >= 0.f ? v2 : 0.01f * v2;
                    float v3 = C[3] + b1; v3 = v3 >= 0.f ? v3 : 0.01f * v3;
                    *(__half2*)(stg + row0 * STG_LDH + col) =
                        __floats2half2_rn(v0 * a0, v1 * a0);
                    *(__half2*)(stg + (row0 + 8) * STG_LDH + col) =
                        __floats2half2_rn(v2 * a1, v3 * a1);
                }
            }
        }
        __syncthreads();   // staging complete

        // ---- pooling: 512 threads, 2 cols each (half2), 16-row chunks ----
        {
            int c0 = (tid & 63) * 2;
            int rb = (tid >> 6) * 16, re = rb + 16;
            float2 f = __half22float2(*(__half2*)(stg + rb * STG_LDH + c0));
            float acc0 = f.x, acc1 = f.y;
            int cg = s_gid[rb];
            for (int r = rb + 1; r < re; ++r) {
                int gr = s_gid[r];
                if (gr != cg) {
                    size_t base = ((size_t)s * G + cg) * D;
                    atomicAdd(&d_pooled[base + c0], acc0);
                    atomicAdd(&d_pooled[base + c0 + 1], acc1);
                    acc0 = 0.f; acc1 = 0.f; cg = gr;
                }
                float2 g2 = __half22float2(*(__half2*)(stg + r * STG_LDH + c0));
                acc0 += g2.x; acc1 += g2.y;
            }
            size_t base = ((size_t)s * G + cg) * D;
            atomicAdd(&d_pooled[base + c0], acc0);
            atomicAdd(&d_pooled[base + c0 + 1], acc1);
        }
        // next-iteration top sync protects stg + B reuse
    }
}

// ---------------- kernel E: xg update, all 3 steps, 16 graphs per block ----------------
#define XG_B 16
__global__ void k_xg_all(const float* __restrict__ tr_w, const float* __restrict__ tr_b,
                         float* __restrict__ xg) {
    __shared__ float cat[XG_B][2 * D];
    int t = threadIdx.x;
    int g0 = blockIdx.x * XG_B;
#pragma unroll
    for (int q = 0; q < XG_B; ++q)
        cat[q][D + t] = xg[(size_t)(g0 + q) * D + t];

#pragma unroll 1
    for (int s = 0; s < S; ++s) {
#pragma unroll
        for (int q = 0; q < XG_B; ++q)
            cat[q][t] = d_pooled[((size_t)s * G + g0 + q) * D + t];
        __syncthreads();
        const float* W = tr_w + (size_t)s * 2 * D * D;
        float bias = tr_b[s * D + t];
        float acc[XG_B];
#pragma unroll
        for (int q = 0; q < XG_B; ++q) acc[q] = bias;
        for (int k = 0; k < 2 * D; ++k) {
            float w = W[(size_t)k * D + t];
#pragma unroll
            for (int q = 0; q < XG_B; ++q) acc[q] += cat[q][k] * w;
        }
        __syncthreads();   // all reads of cat done before update
#pragma unroll
        for (int q = 0; q < XG_B; ++q) {
            float v = acc[q] >= 0.f ? acc[q] : 0.01f * acc[q];
            cat[q][D + t] = v + cat[q][D + t];
        }
        __syncthreads();
    }
#pragma unroll
    for (int q = 0; q < XG_B; ++q)
        xg[(size_t)(g0 + q) * D + t] = cat[q][D + t];
}

// ---------------- host launcher ----------------
extern "C" void kernel_launch(void* const* d_in, const int* in_sizes, int n_in,
                              void* d_out, int out_size) {
    const float* x   = (const float*)d_in[0];
    const float* xg0 = (const float*)d_in[1];
    int N = in_sizes[0] / D;

    int bi = 4;
    for (int i = 1; i < n_in; ++i)
        if (in_sizes[i] == N) { bi = i; break; }
    const int* batch = (const int*)d_in[bi];

    int wi = -1;
    for (int i = 2; i + 5 < n_in; ++i)
        if (in_sizes[i] == S * D && in_sizes[i + 1] == S) { wi = i; break; }
    if (wi < 0) wi = (n_in >= 12) ? 6 : 5;
    const float* gate_w = (const float*)d_in[wi];
    const float* gate_b = (const float*)d_in[wi + 1];
    const float* feat_w = (const float*)d_in[wi + 2];
    const float* feat_b = (const float*)d_in[wi + 3];
    const float* tr_w   = (const float*)d_in[wi + 4];
    const float* tr_b   = (const float*)d_in[wi + 5];

    float* out_x  = (float*)d_out;
    float* out_xg = out_x + (size_t)N * D;

    cudaFuncSetAttribute(k_feat_pool, cudaFuncAttributeMaxDynamicSharedMemorySize, SMEM_TOTAL);

    int gate_blks = (N + 7) / 8;
    k_gate_misc<<<gate_blks + MISC_BLKS, 256>>>(x, gate_w, gate_b, out_x,
                                                xg0, out_xg, feat_w, batch, N);
    k_softmax<<<G, 128>>>(N);
    k_feat_pool<<<(N + 127) / 128, 512, SMEM_TOTAL>>>(x, feat_b, batch, N);
    k_xg_all<<<G / XG_B, 128>>>(tr_w, tr_b, out_xg);
}

// round 13
// speedup vs baseline: 1.2081x; 1.2081x over previous
#include <cuda_runtime.h>
#include <cuda_fp16.h>
#include <math.h>
#include <stdint.h>

#define D   128
#define G   4096
#define S   3
#define MAXN 1000000

// ---------------- device scratch ----------------
__device__ float d_gates[S * MAXN];
__device__ float d_alpha[S * MAXN];
__device__ int   d_segstart[G + 1];
__device__ float d_pooled[S * G * D];
__device__ __half d_wt_hi[S * D * D];       // W^T fp16  [s][n][k]
__device__ __half d_x16[(size_t)MAXN * D];  // x pre-converted to fp16

// ---------------- helpers ----------------
__device__ __forceinline__ uint32_t smem_u32(const void* p) {
    uint32_t a;
    asm("{ .reg .u64 t; cvta.to.shared.u64 t, %1; cvt.u32.u64 %0, t; }" : "=r"(a) : "l"(p));
    return a;
}

__device__ __forceinline__ void ldsm_x4(uint32_t* r, uint32_t addr) {
    asm volatile("ldmatrix.sync.aligned.m8n8.x4.shared.b16 {%0,%1,%2,%3}, [%4];"
                 : "=r"(r[0]), "=r"(r[1]), "=r"(r[2]), "=r"(r[3]) : "r"(addr));
}

__device__ __forceinline__ void mma16816(float* c, const uint32_t* a, uint32_t b0, uint32_t b1) {
    asm volatile(
        "mma.sync.aligned.m16n8k16.row.col.f32.f16.f16.f32 "
        "{%0,%1,%2,%3}, {%4,%5,%6,%7}, {%8,%9}, {%0,%1,%2,%3};"
        : "+f"(c[0]), "+f"(c[1]), "+f"(c[2]), "+f"(c[3])
        : "r"(a[0]), "r"(a[1]), "r"(a[2]), "r"(a[3]), "r"(b0), "r"(b1));
}

__device__ __forceinline__ void cp_async16(uint32_t dst, const void* src, int src_bytes) {
    asm volatile("cp.async.cg.shared.global [%0], [%1], 16, %2;"
                 :: "r"(dst), "l"(src), "r"(src_bytes) : "memory");
}
#define CP_COMMIT() asm volatile("cp.async.commit_group;" ::: "memory")
#define CP_WAIT0()  asm volatile("cp.async.wait_group 0;" ::: "memory")

// swizzled byte offset within a [128 row][128 fp16] tile (row stride 256B)
__device__ __forceinline__ uint32_t swz(int row, int kbyte) {
    return ((uint32_t)row << 8) + ((uint32_t)kbyte ^ (((uint32_t)row & 7u) << 4));
}

// ---------------- smem layout (bytes) ----------------
#define SM_A      0              // 32KB: x tile fp16 (persistent across steps)
#define SM_B      32768          // 32KB: W^T fp16 (cp.async pipeline)
#define SM_STG    65536          // 34KB: fp16 staging, 128 rows x 136-half stride
#define SM_ALPHA  100352         // 3*128 fp32
#define SM_BIAS   101888         // 3*128 fp32
#define SM_GID    103424         // 128 int
#define SMEM_TOTAL 103936
#define STG_LDH   136            // halves per staging row

// ---------------- kernel A: gate dots + x copy + x16 + misc (merged) ----------------
#define MISC_COPY_BLKS  (G * D / 256)             // 2048
#define MISC_PREP_BLKS  ((S * D * D + 255) / 256) // 192
#define MISC_SEG_BLKS   ((G + 256) / 256)         // 17
#define MISC_BLKS (MISC_COPY_BLKS + MISC_PREP_BLKS + MISC_SEG_BLKS)

__global__ void k_gate_misc(const float* __restrict__ x,
                            const float* __restrict__ gate_w,
                            const float* __restrict__ gate_b,
                            float* __restrict__ out_x,
                            const float* __restrict__ xg, float* __restrict__ out_xg,
                            const float* __restrict__ feat_w,
                            const int* __restrict__ batch, int N) {
    int gate_blks = (N + 7) / 8;
    if ((int)blockIdx.x >= gate_blks) {
        // ---- misc section ----
        int b = blockIdx.x - gate_blks, t = threadIdx.x;
        if (b < MISC_COPY_BLKS) {
            out_xg[b * 256 + t] = xg[b * 256 + t];
        } else if (b < MISC_COPY_BLKS + MISC_PREP_BLKS) {
            int i = (b - MISC_COPY_BLKS) * 256 + t;
            if (i < S * D * D) {
                int s = i / (D * D), r = i % (D * D);
                int n = r / D, k = r % D;
                d_wt_hi[i] = __float2half_rn(feat_w[s * D * D + k * D + n]);
            }
        } else {
            int g = (b - MISC_COPY_BLKS - MISC_PREP_BLKS) * 256 + t;
            if (g > G) return;
            if (g == G) { d_segstart[G] = N; return; }
            int lo = 0, hi = N;
            while (lo < hi) {
                int mid = (lo + hi) >> 1;
                if (batch[mid] < g) lo = mid + 1; else hi = mid;
            }
            d_segstart[g] = lo;
        }
        return;
    }
    // ---- gate + copy + fp16 convert section ----
    __shared__ float gw[S * D];
    int tid = threadIdx.x;
    for (int i = tid; i < S * D; i += blockDim.x) gw[i] = gate_w[i];
    __syncthreads();
    int lane = tid & 31;
    int node = blockIdx.x * 8 + (tid >> 5);
    if (node >= N) return;
    const float4 v = ((const float4*)(x + (size_t)node * D))[lane];
    ((float4*)(out_x + (size_t)node * D))[lane] = v;
    uint2 hp;
    hp.x = (uint32_t)__half_as_ushort(__float2half_rn(v.x)) |
           ((uint32_t)__half_as_ushort(__float2half_rn(v.y)) << 16);
    hp.y = (uint32_t)__half_as_ushort(__float2half_rn(v.z)) |
           ((uint32_t)__half_as_ushort(__float2half_rn(v.w)) << 16);
    ((uint2*)(d_x16 + (size_t)node * D))[lane] = hp;
#pragma unroll
    for (int s = 0; s < S; ++s) {
        const float* g = gw + s * D + lane * 4;
        float d = v.x * g[0] + v.y * g[1] + v.z * g[2] + v.w * g[3];
#pragma unroll
        for (int o = 16; o > 0; o >>= 1) d += __shfl_xor_sync(0xffffffffu, d, o);
        if (lane == 0) d_gates[s * N + node] = d + gate_b[s];
    }
}

// ---------------- kernel C: per-graph softmax -> alpha; zero pooled ----------------
__global__ void k_softmax(int N) {
    int g = blockIdx.x, t = threadIdx.x;
#pragma unroll
    for (int s = 0; s < S; ++s) d_pooled[(s * G + g) * D + t] = 0.f;
    int a = d_segstart[g], b = d_segstart[g + 1];
    if (a >= b) return;
    __shared__ float red[S][4];
    int wid = t >> 5, lane = t & 31;
    float mx[S];
#pragma unroll
    for (int s = 0; s < S; ++s) mx[s] = -INFINITY;
    for (int i = a + t; i < b; i += 128)
#pragma unroll
        for (int s = 0; s < S; ++s) mx[s] = fmaxf(mx[s], d_gates[s * N + i]);
#pragma unroll
    for (int s = 0; s < S; ++s) {
#pragma unroll
        for (int o = 16; o > 0; o >>= 1) mx[s] = fmaxf(mx[s], __shfl_xor_sync(~0u, mx[s], o));
        if (lane == 0) red[s][wid] = mx[s];
    }
    __syncthreads();
#pragma unroll
    for (int s = 0; s < S; ++s)
        mx[s] = fmaxf(fmaxf(red[s][0], red[s][1]), fmaxf(red[s][2], red[s][3]));
    __syncthreads();
    float sm[S] = {0.f, 0.f, 0.f};
    for (int i = a + t; i < b; i += 128)
#pragma unroll
        for (int s = 0; s < S; ++s) sm[s] += expf(d_gates[s * N + i] - mx[s]);
#pragma unroll
    for (int s = 0; s < S; ++s) {
#pragma unroll
        for (int o = 16; o > 0; o >>= 1) sm[s] += __shfl_xor_sync(~0u, sm[s], o);
        if (lane == 0) red[s][wid] = sm[s];
    }
    __syncthreads();
    float inv[S];
#pragma unroll
    for (int s = 0; s < S; ++s)
        inv[s] = 1.f / (red[s][0] + red[s][1] + red[s][2] + red[s][3]);
    for (int i = a + t; i < b; i += 128)
#pragma unroll
        for (int s = 0; s < S; ++s)
            d_alpha[s * N + i] = expf(d_gates[s * N + i] - mx[s]) * inv[s];
}

// ---------------- kernel D: pipelined fp16 HMMA (R10 design) ----------------
__global__ void __launch_bounds__(512, 2)
k_feat_pool(const float* __restrict__ feat_b,
            const int* __restrict__ batch, int N) {
    extern __shared__ char smem[];
    uint32_t sm = smem_u32(smem);
    __half* stg    = (__half*)(smem + SM_STG);
    float* s_alpha = (float*)(smem + SM_ALPHA);
    float* s_bias  = (float*)(smem + SM_BIAS);
    int*   s_gid   = (int*)(smem + SM_GID);

    int tid = threadIdx.x;
    int wid = tid >> 5, lane = tid & 31;
    int r0 = blockIdx.x * 128;
    int rows = min(128, N - r0);

    // ---- prologue: cp.async A tile (fp16) + B(0) ----
#pragma unroll
    for (int i = 0; i < 4; ++i) {
        int idx = i * 512 + tid;           // 2048 x 16B
        int row = idx >> 4, kpart = idx & 15;
        cp_async16(sm + SM_A + swz(row, kpart * 16),
                   d_x16 + (size_t)(r0 + row) * D + kpart * 8,
                   (row < rows) ? 16 : 0);
    }
    {
        const __half* wh = d_wt_hi;        // step 0
#pragma unroll
        for (int i = 0; i < 4; ++i) {
            int idx = i * 512 + tid;
            int row = idx >> 4, kpart = idx & 15;
            cp_async16(sm + SM_B + swz(row, kpart * 16), wh + row * D + kpart * 8, 16);
        }
    }
    CP_COMMIT();

    // prefetch alpha/bias for all 3 steps + gid
    if (tid < 384) {
        int s = tid >> 7, t = tid & 127;
        s_bias[tid]  = feat_b[s * D + t];
        s_alpha[tid] = (t < rows) ? d_alpha[s * N + r0 + t] : 0.f;
    }
    if (tid < 128) {
        int rr = min(tid, rows - 1);
        s_gid[tid] = batch[r0 + rr];
    }

    // warp tiling: 4 m-blocks (32 rows) x 4 n-blocks (32 cols), 16 warps
    int mbase = (wid & 3) * 32;
    int nbase = (wid >> 2) * 32;
    int r15 = lane & 15;
    uint32_t swx = ((uint32_t)lane & 7u) << 4;
    int khalf = (lane >> 4) << 4;
    int grp   = lane >> 2, tc = (lane & 3) * 2;

#pragma unroll 1
    for (int s = 0; s < S; ++s) {
        CP_WAIT0();
        __syncthreads();   // B(s) + (s==0: A, alpha, bias, gid) ready; stg free

        float c[8][4];   // [mi*4 + nq*2 + j][4]
#pragma unroll
        for (int i = 0; i < 8; ++i)
#pragma unroll
            for (int j = 0; j < 4; ++j) c[i][j] = 0.f;

        // ---- MMA: c = x_hi * W_hi ----
#pragma unroll
        for (int ks = 0; ks < 8; ++ks) {
            int kb = ks * 32 + khalf;
            uint32_t ah[2][4];
#pragma unroll
            for (int mi = 0; mi < 2; ++mi) {
                uint32_t aoff = ((uint32_t)(mbase + mi * 16 + r15) << 8) + ((uint32_t)kb ^ swx);
                ldsm_x4(ah[mi], sm + SM_A + aoff);
            }
#pragma unroll
            for (int nq = 0; nq < 2; ++nq) {
                uint32_t bh[4];
                uint32_t boff = ((uint32_t)(nbase + nq * 16 + r15) << 8) + ((uint32_t)kb ^ swx);
                ldsm_x4(bh, sm + SM_B + boff);
#pragma unroll
                for (int mi = 0; mi < 2; ++mi) {
                    mma16816(c[mi * 4 + nq * 2],     ah[mi], bh[0], bh[2]);
                    mma16816(c[mi * 4 + nq * 2 + 1], ah[mi], bh[1], bh[3]);
                }
            }
        }
        __syncthreads();   // all warps done reading B(s)

        // ---- prefetch B(s+1), overlapped with epilogue + pooling ----
        if (s + 1 < S) {
            const __half* wh = d_wt_hi + (s + 1) * D * D;
#pragma unroll
            for (int i = 0; i < 4; ++i) {
                int idx = i * 512 + tid;
                int row = idx >> 4, kpart = idx & 15;
                cp_async16(sm + SM_B + swz(row, kpart * 16), wh + row * D + kpart * 8, 16);
            }
            CP_COMMIT();
        }

        // ---- single-phase epilogue: bias + leaky + alpha -> fp16 staging ----
#pragma unroll
        for (int mi = 0; mi < 2; ++mi) {
            int row0 = mbase + mi * 16 + grp;
            float a0 = s_alpha[s * 128 + row0], a1 = s_alpha[s * 128 + row0 + 8];
#pragma unroll
            for (int nq = 0; nq < 2; ++nq) {
#pragma unroll
                for (int j = 0; j < 2; ++j) {
                    int col = nbase + nq * 16 + j * 8 + tc;
                    float b0 = s_bias[s * 128 + col], b1 = s_bias[s * 128 + col + 1];
                    float* C = c[mi * 4 + nq * 2 + j];
                    float v0 = C[0] + b0; v0 = v0 >= 0.f ? v0 : 0.01f * v0;
                    float v1 = C[1] + b1; v1 = v1 >= 0.f ? v1 : 0.01f * v1;
                    float v2 = C[2] + b0; v2 = v2 >= 0.f ? v2 : 0.01f * v2;
                    float v3 = C[3] + b1; v3 = v3 >= 0.f ? v3 : 0.01f * v3;
                    *(__half2*)(stg + row0 * STG_LDH + col) =
                        __floats2half2_rn(v0 * a0, v1 * a0);
                    *(__half2*)(stg + (row0 + 8) * STG_LDH + col) =
                        __floats2half2_rn(v2 * a1, v3 * a1);
                }
            }
        }
        __syncthreads();   // staging complete

        // ---- pooling: 512 threads, 2 cols each (half2), 16-row chunks ----
        {
            int c0 = (tid & 63) * 2;
            int rb = (tid >> 6) * 16, re = rb + 16;
            float2 f = __half22float2(*(__half2*)(stg + rb * STG_LDH + c0));
            float acc0 = f.x, acc1 = f.y;
            int cg = s_gid[rb];
            for (int r = rb + 1; r < re; ++r) {
                int gr = s_gid[r];
                if (gr != cg) {
                    size_t base = ((size_t)s * G + cg) * D;
                    atomicAdd(&d_pooled[base + c0], acc0);
                    atomicAdd(&d_pooled[base + c0 + 1], acc1);
                    acc0 = 0.f; acc1 = 0.f; cg = gr;
                }
                float2 g2 = __half22float2(*(__half2*)(stg + r * STG_LDH + c0));
                acc0 += g2.x; acc1 += g2.y;
            }
            size_t base = ((size_t)s * G + cg) * D;
            atomicAdd(&d_pooled[base + c0], acc0);
            atomicAdd(&d_pooled[base + c0 + 1], acc1);
        }
        // next-iteration top sync protects stg + B reuse
    }
}

// ---------------- kernel E: xg update, k-split parallel, 8 graphs x 512 thr ----------------
#define XG_B 8
__global__ void __launch_bounds__(512)
k_xg_all(const float* __restrict__ tr_w, const float* __restrict__ tr_b,
         float* __restrict__ xg) {
    __shared__ float cat[XG_B][2 * D];      // 8KB
    __shared__ float psum[4][XG_B][D];      // 16KB
    int t = threadIdx.x;                    // 512
    int c = t & 127, kq = t >> 7;           // column, k-quarter
    int g0 = blockIdx.x * XG_B;

    // load residual xg into cat[:, D:2D)
    for (int i = t; i < XG_B * D; i += 512)
        cat[i >> 7][D + (i & 127)] = xg[(size_t)(g0 + (i >> 7)) * D + (i & 127)];

#pragma unroll 1
    for (int s = 0; s < S; ++s) {
        for (int i = t; i < XG_B * D; i += 512)
            cat[i >> 7][i & 127] = d_pooled[((size_t)s * G + g0 + (i >> 7)) * D + (i & 127)];
        __syncthreads();

        const float* W = tr_w + (size_t)s * 2 * D * D;
        float acc[XG_B];
#pragma unroll
        for (int q = 0; q < XG_B; ++q) acc[q] = 0.f;
        int k0 = kq * 64;
#pragma unroll 8
        for (int k = k0; k < k0 + 64; ++k) {
            float w = W[(size_t)k * D + c];
#pragma unroll
            for (int q = 0; q < XG_B; ++q) acc[q] += cat[q][k] * w;
        }
#pragma unroll
        for (int q = 0; q < XG_B; ++q) psum[kq][q][c] = acc[q];
        __syncthreads();

        // finalize: threads with kq==0 (t < 128)
        if (kq == 0) {
            float bias = tr_b[s * D + c];
#pragma unroll
            for (int q = 0; q < XG_B; ++q) {
                float v = psum[0][q][c] + psum[1][q][c] + psum[2][q][c] + psum[3][q][c] + bias;
                v = v >= 0.f ? v : 0.01f * v;
                cat[q][D + c] = v + cat[q][D + c];
            }
        }
        __syncthreads();
    }
    for (int i = t; i < XG_B * D; i += 512)
        xg[(size_t)(g0 + (i >> 7)) * D + (i & 127)] = cat[i >> 7][D + (i & 127)];
}

// ---------------- host launcher ----------------
extern "C" void kernel_launch(void* const* d_in, const int* in_sizes, int n_in,
                              void* d_out, int out_size) {
    const float* x   = (const float*)d_in[0];
    const float* xg0 = (const float*)d_in[1];
    int N = in_sizes[0] / D;

    int bi = 4;
    for (int i = 1; i < n_in; ++i)
        if (in_sizes[i] == N) { bi = i; break; }
    const int* batch = (const int*)d_in[bi];

    int wi = -1;
    for (int i = 2; i + 5 < n_in; ++i)
        if (in_sizes[i] == S * D && in_sizes[i + 1] == S) { wi = i; break; }
    if (wi < 0) wi = (n_in >= 12) ? 6 : 5;
    const float* gate_w = (const float*)d_in[wi];
    const float* gate_b = (const float*)d_in[wi + 1];
    const float* feat_w = (const float*)d_in[wi + 2];
    const float* feat_b = (const float*)d_in[wi + 3];
    const float* tr_w   = (const float*)d_in[wi + 4];
    const float* tr_b   = (const float*)d_in[wi + 5];

    float* out_x  = (float*)d_out;
    float* out_xg = out_x + (size_t)N * D;

    cudaFuncSetAttribute(k_feat_pool, cudaFuncAttributeMaxDynamicSharedMemorySize, SMEM_TOTAL);

    int gate_blks = (N + 7) / 8;
    k_gate_misc<<<gate_blks + MISC_BLKS, 256>>>(x, gate_w, gate_b, out_x,
                                                xg0, out_xg, feat_w, batch, N);
    k_softmax<<<G, 128>>>(N);
    k_feat_pool<<<(N + 127) / 128, 512, SMEM_TOTAL>>>(feat_b, batch, N);
    k_xg_all<<<G / XG_B, 512>>>(tr_w, tr_b, out_xg);
}